// round 4
// baseline (speedup 1.0000x reference)
#include <cuda_runtime.h>

// CTC batch cost (keras.backend.ctc_batch_cost semantics, full lengths,
// blank = C-1). Faithful log-space forward recursion mirroring the JAX
// reference op-for-op. One warp per batch row; 5 states per lane.
//
// y_true [B=512, L=64] int32, y_pred [B=512, T=512, C=96] f32,
// out [B,1] f32.  S = 2L+1 = 129 states, blank = 95.

constexpr int T_DIM = 512;
constexpr int C_DIM = 96;
constexpr int L_DIM = 64;
constexpr int S_DIM = 2 * L_DIM + 1;   // 129
constexpr int BLANK = C_DIM - 1;       // 95
constexpr int KPL   = 5;               // states per lane (lanes 0..25 real)
constexpr float EPSF = 1e-7f;          // keras epsilon
constexpr float NEGF = -1e30f;         // reference's log-space -inf

#define FULLMASK 0xffffffffu

// logaddexp, same formulation as jnp: max + log1p(exp(min-max)).
__device__ __forceinline__ float lax(float a, float b) {
    float m = fmaxf(a, b);
    float n = fminf(a, b);
    return m + __logf(1.f + __expf(n - m));
}

__global__ void __launch_bounds__(128, 1)
ctc_fwd_kernel(const int* __restrict__ y_true,
               const float* __restrict__ y_pred,
               float* __restrict__ out, int B)
{
    const int warp = threadIdx.x >> 5;
    const int lane = threadIdx.x & 31;
    const int b = blockIdx.x * 4 + warp;
    if (b >= B) return;

    const float* __restrict__ P = y_pred + (size_t)b * (size_t)(T_DIM * C_DIM);
    const int* __restrict__ lab = y_true + (size_t)b * L_DIM;

    // Static per-state info. State s = lane*KPL + k.
    int cls[KPL];
    float skf[KPL];
#pragma unroll
    for (int k = 0; k < KPL; ++k) {
        int s = lane * KPL + k;
        int c = BLANK;
        float sk = 0.f;
        if (s < S_DIM && (s & 1)) {
            int j = (s - 1) >> 1;
            c = lab[j];
            if (c < 0) c = 0;
            if (c > C_DIM - 1) c = C_DIM - 1;
            if (s >= 3 && c != lab[j - 1]) sk = 1.f;
        }
        cls[k] = c;
        skf[k] = sk;
    }

    // log-alpha at t=0: state0 = log p(blank), state1 = log p(l0), rest NEG.
    float la[KPL];
#pragma unroll
    for (int k = 0; k < KPL; ++k) la[k] = NEGF;
    if (lane == 0) {
        la[0] = __logf(P[cls[0]] + EPSF);
        la[1] = __logf(P[cls[1]] + EPSF);
    }

    // Double-buffered 8-step chunks of gathered probabilities (+EPS folded).
    float bufA[8][KPL], bufB[8][KPL];

    auto load_chunk = [&](float (&buf)[8][KPL], int tbase) {
#pragma unroll
        for (int i = 0; i < 8; ++i) {
            int t = tbase + i;
            if (t > T_DIM - 1) t = T_DIM - 1;   // clamp; guarded at compute
            const float* row = P + t * C_DIM;
#pragma unroll
            for (int k = 0; k < KPL; ++k)
                buf[i][k] = __ldg(row + cls[k]) + EPSF;
        }
    };

    auto step = [&](const float (&p)[KPL]) {
        float lg[KPL];
#pragma unroll
        for (int k = 0; k < KPL; ++k) lg[k] = __logf(p[k]);
        // boundary states from previous lane (s-1, s-2 for k=0/1)
        float am1 = __shfl_up_sync(FULLMASK, la[KPL - 1], 1);
        float am2 = __shfl_up_sync(FULLMASK, la[KPL - 2], 1);
        if (lane == 0) { am1 = NEGF; am2 = NEGF; }
        float na[KPL];
        {
            float a  = lax(la[0], am1);
            float a2 = lax(a, am2);
            na[0] = (skf[0] != 0.f ? a2 : a) + lg[0];
        }
        {
            float a  = lax(la[1], la[0]);
            float a2 = lax(a, am1);
            na[1] = (skf[1] != 0.f ? a2 : a) + lg[1];
        }
#pragma unroll
        for (int k = 2; k < KPL; ++k) {
            float a  = lax(la[k], la[k - 1]);
            float a2 = lax(a, la[k - 2]);
            na[k] = (skf[k] != 0.f ? a2 : a) + lg[k];
        }
#pragma unroll
        for (int k = 0; k < KPL; ++k) la[k] = na[k];
    };

    // Steps t = 1 .. T-1 (511 steps) in 64 chunks of 8 (last chunk 7 real).
    load_chunk(bufA, 1);
#pragma unroll 1
    for (int ci = 0; ci < 64; ci += 2) {
        const int tb = 1 + ci * 8;
        load_chunk(bufB, tb + 8);          // prefetch next chunk
#pragma unroll
        for (int i = 0; i < 8; ++i)
            if (tb + i < T_DIM) step(bufA[i]);
        load_chunk(bufA, tb + 16);         // prefetch chunk after next
#pragma unroll
        for (int i = 0; i < 8; ++i)
            if (tb + 8 + i < T_DIM) step(bufB[i]);
    }

    // loss = -logaddexp(alpha[S-1], alpha[S-2])
    // state 127 = lane 25 slot 2, state 128 = lane 25 slot 3
    float v128 = __shfl_sync(FULLMASK, la[3], 25);
    float v127 = __shfl_sync(FULLMASK, la[2], 25);
    if (lane == 0)
        out[b] = -lax(v128, v127);
}

extern "C" void kernel_launch(void* const* d_in, const int* in_sizes, int n_in,
                              void* d_out, int out_size)
{
    // y_true is the small input (B*L), y_pred the large one (B*T*C).
    int iy = 0, ip = 1;
    if (n_in >= 2 && in_sizes[0] > in_sizes[1]) { iy = 1; ip = 0; }
    const int* y_true = (const int*)d_in[iy];
    const float* y_pred = (const float*)d_in[ip];
    float* out = (float*)d_out;
    int B = in_sizes[iy] / L_DIM;          // 512
    int grid = (B + 3) / 4;                // 4 warps (rows) per block
    ctc_fwd_kernel<<<grid, 128>>>(y_true, y_pred, out, B);
}

// round 7
// speedup vs baseline: 2.9195x; 2.9195x over previous
#include <cuda_runtime.h>
#include <math.h>

// CTC batch cost (keras.backend.ctc_batch_cost, full lengths, blank=C-1).
// Linear-space forward recursion with per-lane power-of-2 renormalization.
// Exact scaling: empty lanes adopt the nearest-left nonempty lane's exponent
// warp-wide each renorm (ballot scan), so cross-lane conversion factors never
// saturate. No MUFU in the hot loop.
// One warp per batch row; 5 states per lane (lanes 0..25 real).
//
// y_true [B=512, L=64] int32, y_pred [B=512, T=512, C=96] f32, out [B,1] f32.

constexpr int T_DIM = 512;
constexpr int C_DIM = 96;
constexpr int L_DIM = 64;
constexpr int S_DIM = 2 * L_DIM + 1;   // 129
constexpr int BLANK = C_DIM - 1;       // 95
constexpr int KPL   = 5;
constexpr float EPSF = 1e-7f;

#define FULLMASK 0xffffffffu

__global__ void __launch_bounds__(128, 1)
ctc_fwd_kernel(const int* __restrict__ y_true,
               const float* __restrict__ y_pred,
               float* __restrict__ out, int B)
{
    const int warp = threadIdx.x >> 5;
    const int lane = threadIdx.x & 31;
    const int b = blockIdx.x * 4 + warp;
    if (b >= B) return;

    const float* __restrict__ P = y_pred + (size_t)b * (size_t)(T_DIM * C_DIM);
    const int* __restrict__ lab = y_true + (size_t)b * L_DIM;

    // Static per-state info. State s = lane*KPL + k.
    int cls[KPL];
    float skf[KPL];
#pragma unroll
    for (int k = 0; k < KPL; ++k) {
        int s = lane * KPL + k;
        int c = BLANK;
        float sk = 0.f;
        if (s < S_DIM && (s & 1)) {
            int j = (s - 1) >> 1;
            c = lab[j];
            if (c < 0) c = 0;
            if (c > C_DIM - 1) c = C_DIM - 1;
            if (s >= 3 && c != lab[j - 1]) sk = 1.f;
        }
        cls[k] = c;
        skf[k] = sk;
    }

    // alpha (linear, lane-scaled): true alpha[s] = a[k] * 2^E.
    float a[KPL];
#pragma unroll
    for (int k = 0; k < KPL; ++k) a[k] = 0.f;
    if (lane == 0) {
        a[0] = P[cls[0]] + EPSF;
        a[1] = P[cls[1]] + EPSF;
    }
    int   E = 0;      // per-lane power-of-2 offset
    float f = 1.f;    // 2^(E_prevlane - E), refreshed at each renorm

    // Double-buffered 8-step chunks of gathered probabilities (+EPS folded).
    float bufA[8][KPL], bufB[8][KPL];

    auto load_chunk = [&](float (&buf)[8][KPL], int tbase) {
#pragma unroll
        for (int i = 0; i < 8; ++i) {
            int t = tbase + i;
            if (t > T_DIM - 1) t = T_DIM - 1;   // clamp; guarded at compute
            const float* row = P + t * C_DIM;
#pragma unroll
            for (int k = 0; k < KPL; ++k)
                buf[i][k] = __ldg(row + cls[k]) + EPSF;
        }
    };

    auto step = [&](const float (&p)[KPL]) {
        float am1 = __shfl_up_sync(FULLMASK, a[KPL - 1], 1);
        float am2 = __shfl_up_sync(FULLMASK, a[KPL - 2], 1);
        if (lane == 0) { am1 = 0.f; am2 = 0.f; }
        am1 *= f;
        am2 *= f;
        float n0 = fmaf(skf[0], am2,  a[0] + am1)  * p[0];
        float n1 = fmaf(skf[1], am1,  a[1] + a[0]) * p[1];
        float n2 = fmaf(skf[2], a[0], a[2] + a[1]) * p[2];
        float n3 = fmaf(skf[3], a[1], a[3] + a[2]) * p[3];
        float n4 = fmaf(skf[4], a[2], a[4] + a[3]) * p[4];
        a[0] = n0; a[1] = n1; a[2] = n2; a[3] = n3; a[4] = n4;
    };

    auto renorm = [&]() {
        float m = fmaxf(fmaxf(fmaxf(a[0], a[1]), fmaxf(a[2], a[3])), a[4]);
        bool ne = (m > 0.f);                 // denormal max counts as nonempty
        if (ne) {
            int mb = __float_as_int(m) >> 23;
            if (mb == 0) {                   // denormal max: exact pre-scale up
                const float up = 0x1p126f;
#pragma unroll
                for (int k = 0; k < KPL; ++k) a[k] *= up;
                E -= 126;
                m *= up;
                mb = __float_as_int(m) >> 23;
            }
            float scale = __int_as_float((254 - mb) << 23);   // exact 2^{-e}
#pragma unroll
            for (int k = 0; k < KPL; ++k) a[k] *= scale;
            E += mb - 127;
        }
        // Warp-wide adoption: empty lanes take E of nearest nonempty lane
        // to the left (post-update), so stale exponents never accumulate.
        unsigned bm = __ballot_sync(FULLMASK, ne);
        unsigned below = bm & ((2u << lane) - 1u);   // bits 0..lane
        int src = below ? (31 - __clz(below)) : lane;
        int Ead = __shfl_sync(FULLMASK, E, src);
        if (!ne) E = Ead;
        int Ep = __shfl_up_sync(FULLMASK, E, 1);     // neighbor's new E
        int d = (lane == 0) ? 0 : (Ep - E);
        d = max(-127, min(120, d));
        f = (d <= -127) ? 0.f : __int_as_float((d + 127) << 23); // exact 2^d
    };

    // Steps t = 1 .. T-1 (511 steps) in 64 chunks of 8 (last step skipped).
    load_chunk(bufA, 1);
#pragma unroll 1
    for (int ci = 0; ci < 64; ci += 2) {
        const int tb = 1 + ci * 8;
        load_chunk(bufB, tb + 8);          // prefetch next chunk
#pragma unroll
        for (int i = 0; i < 8; ++i) {
            if (tb + i < T_DIM) step(bufA[i]);
            if (i == 3 || i == 7) renorm();
        }
        load_chunk(bufA, tb + 16);         // prefetch chunk after next
#pragma unroll
        for (int i = 0; i < 8; ++i) {
            if (tb + 8 + i < T_DIM) step(bufB[i]);
            if (i == 3 || i == 7) renorm();
        }
    }

    // loss = -log(alpha[127] + alpha[128]); both live in lane 25 (k=2,3).
    if (lane == 25) {
        double s = (double)(a[2] + a[3]);
        double loss = -(log(s) + (double)E * 0.6931471805599453);
        out[b] = (float)loss;
    }
}

extern "C" void kernel_launch(void* const* d_in, const int* in_sizes, int n_in,
                              void* d_out, int out_size)
{
    // y_true is the small input (B*L), y_pred the large one (B*T*C).
    int iy = 0, ip = 1;
    if (n_in >= 2 && in_sizes[0] > in_sizes[1]) { iy = 1; ip = 0; }
    const int* y_true = (const int*)d_in[iy];
    const float* y_pred = (const float*)d_in[ip];
    float* out = (float*)d_out;
    int B = in_sizes[iy] / L_DIM;          // 512
    int grid = (B + 3) / 4;                // 4 warps (rows) per block
    ctc_fwd_kernel<<<grid, 128>>>(y_true, y_pred, out, B);
}

// round 8
// speedup vs baseline: 4.6632x; 1.5973x over previous
#include <cuda_runtime.h>
#include <math.h>

// CTC batch cost (keras.backend.ctc_batch_cost, full lengths, blank=C-1).
// Linear-space forward recursion, per-lane power-of-2 renorm (exact).
// Streaming: coalesced cp.async of 8-row chunks into a 4-stage per-warp
// smem ring; probability gathers become LDS. One warp per batch row,
// 5 states per lane (lanes 0..25 real).
//
// y_true [B=512, L=64] int32, y_pred [B=512, T=512, C=96] f32, out [B,1] f32.

constexpr int T_DIM = 512;
constexpr int C_DIM = 96;
constexpr int L_DIM = 64;
constexpr int S_DIM = 2 * L_DIM + 1;   // 129
constexpr int BLANK = C_DIM - 1;       // 95
constexpr int KPL   = 5;
constexpr int CH    = 8;               // t-rows per chunk
constexpr int STG   = 4;               // smem ring stages
constexpr int WPB   = 4;               // warps (rows) per block
constexpr int NCHUNK = T_DIM / CH;     // 64
constexpr float EPSF = 1e-7f;

#define FULLMASK 0xffffffffu

__global__ void __launch_bounds__(128, 1)
ctc_fwd_kernel(const int* __restrict__ y_true,
               const float* __restrict__ y_pred,
               float* __restrict__ out, int B)
{
    __shared__ float sbuf[WPB][STG][CH * C_DIM];   // 4*4*768*4B = 48KB

    const int warp = threadIdx.x >> 5;
    const int lane = threadIdx.x & 31;
    const int b = blockIdx.x * WPB + warp;
    if (b >= B) return;   // never taken for B=512 with this grid

    const float* __restrict__ P = y_pred + (size_t)b * (size_t)(T_DIM * C_DIM);
    const int* __restrict__ lab = y_true + (size_t)b * L_DIM;

    // Static per-state info. State s = lane*KPL + k.
    int cls[KPL];
    float skf[KPL];
#pragma unroll
    for (int k = 0; k < KPL; ++k) {
        int s = lane * KPL + k;
        int c = BLANK;
        float sk = 0.f;
        if (s < S_DIM && (s & 1)) {
            int j = (s - 1) >> 1;
            c = lab[j];
            if (c < 0) c = 0;
            if (c > C_DIM - 1) c = C_DIM - 1;
            if (s >= 3 && c != lab[j - 1]) sk = 1.f;
        }
        cls[k] = c;
        skf[k] = sk;
    }

    // alpha (linear, lane-scaled): true alpha[s] = a[k] * 2^E.
    float a[KPL];
#pragma unroll
    for (int k = 0; k < KPL; ++k) a[k] = 0.f;
    if (lane == 0) {
        a[0] = P[cls[0]] + EPSF;
        a[1] = P[cls[1]] + EPSF;
    }
    int   E = 0;
    float f = 1.f;

    // ---- producer: coalesced cp.async of one 8-row chunk (3072 B) ----
    auto issue = [&](int c) {
        const float4* g = (const float4*)(P + (size_t)c * (CH * C_DIM));
        unsigned sa = (unsigned)__cvta_generic_to_shared(sbuf[warp][c & (STG - 1)]);
#pragma unroll
        for (int j = 0; j < 6; ++j) {             // 192 float4 / 32 lanes
            int idx = lane + 32 * j;
            asm volatile("cp.async.cg.shared.global [%0], [%1], 16;\n"
                         :: "r"(sa + idx * 16), "l"(g + idx));
        }
        asm volatile("cp.async.commit_group;\n" ::: "memory");
    };

    // ---- gather probs for time t from smem ----
    auto ldp = [&](int t, float (&pp)[KPL]) {
        const float* rb = sbuf[warp][(t >> 3) & (STG - 1)] + (t & (CH - 1)) * C_DIM;
#pragma unroll
        for (int k = 0; k < KPL; ++k) pp[k] = rb[cls[k]];
    };

    auto step = [&](const float (&p)[KPL]) {
        float am1 = __shfl_up_sync(FULLMASK, a[KPL - 1], 1);
        float am2 = __shfl_up_sync(FULLMASK, a[KPL - 2], 1);
        if (lane == 0) { am1 = 0.f; am2 = 0.f; }
        am1 *= f;
        am2 *= f;
        float q0 = p[0] + EPSF, q1 = p[1] + EPSF, q2 = p[2] + EPSF,
              q3 = p[3] + EPSF, q4 = p[4] + EPSF;
        float n0 = fmaf(skf[0], am2,  a[0] + am1)  * q0;
        float n1 = fmaf(skf[1], am1,  a[1] + a[0]) * q1;
        float n2 = fmaf(skf[2], a[0], a[2] + a[1]) * q2;
        float n3 = fmaf(skf[3], a[1], a[3] + a[2]) * q3;
        float n4 = fmaf(skf[4], a[2], a[4] + a[3]) * q4;
        a[0] = n0; a[1] = n1; a[2] = n2; a[3] = n3; a[4] = n4;
    };

    auto renorm = [&]() {
        float m = fmaxf(fmaxf(fmaxf(a[0], a[1]), fmaxf(a[2], a[3])), a[4]);
        bool ne = (m > 0.f);
        if (ne) {
            int mb = __float_as_int(m) >> 23;
            if (mb == 0) {                         // denormal max: exact boost
                const float up = 0x1p126f;
#pragma unroll
                for (int k = 0; k < KPL; ++k) a[k] *= up;
                E -= 126;
                m *= up;
                mb = __float_as_int(m) >> 23;
            }
            float scale = __int_as_float((254 - mb) << 23);   // exact 2^{-e}
#pragma unroll
            for (int k = 0; k < KPL; ++k) a[k] *= scale;
            E += mb - 127;
        }
        unsigned bm = __ballot_sync(FULLMASK, ne);
        unsigned below = bm & ((2u << lane) - 1u);
        int src = below ? (31 - __clz(below)) : lane;
        int Ead = __shfl_sync(FULLMASK, E, src);
        if (!ne) E = Ead;
        int Ep = __shfl_up_sync(FULLMASK, E, 1);
        int d = (lane == 0) ? 0 : (Ep - E);
        d = max(-127, min(120, d));
        f = (d <= -127) ? 0.f : __int_as_float((d + 127) << 23); // exact 2^d
    };

    // ---- pipeline: 3-deep prologue, wait keeps chunks c and c+1 resident ----
    issue(0); issue(1); issue(2);

    float pc[KPL];
#pragma unroll 1
    for (int c = 0; c < NCHUNK; ++c) {
        if (c + 3 < NCHUNK) issue(c + 3);
        if (c < NCHUNK - 3)
            asm volatile("cp.async.wait_group 2;\n" ::: "memory");
        else
            asm volatile("cp.async.wait_group 0;\n" ::: "memory");
        __syncwarp();

        if (c == 0) ldp(1, pc);
#pragma unroll
        for (int i = 0; i < CH; ++i) {
            int t = c * CH + i;
            if (c == 0 && i == 0) continue;       // t=0 is the init state
            float pn[KPL];
            int tn = (t + 1 < T_DIM) ? (t + 1) : (T_DIM - 1);
            ldp(tn, pn);                          // prefetch next step's probs
            step(pc);
            if ((t & 3) == 3) renorm();
#pragma unroll
            for (int k = 0; k < KPL; ++k) pc[k] = pn[k];
        }
    }

    // loss = -log(alpha[127] + alpha[128]); both live in lane 25 (k=2,3).
    if (lane == 25) {
        double s = (double)(a[2] + a[3]);
        double loss = -(log(s) + (double)E * 0.6931471805599453);
        out[b] = (float)loss;
    }
}

extern "C" void kernel_launch(void* const* d_in, const int* in_sizes, int n_in,
                              void* d_out, int out_size)
{
    // y_true is the small input (B*L), y_pred the large one (B*T*C).
    int iy = 0, ip = 1;
    if (n_in >= 2 && in_sizes[0] > in_sizes[1]) { iy = 1; ip = 0; }
    const int* y_true = (const int*)d_in[iy];
    const float* y_pred = (const float*)d_in[ip];
    float* out = (float*)d_out;
    int B = in_sizes[iy] / L_DIM;          // 512
    int grid = (B + WPB - 1) / WPB;        // 4 warps (rows) per block
    ctc_fwd_kernel<<<grid, 128>>>(y_true, y_pred, out, B);
}

// round 10
// speedup vs baseline: 5.9540x; 1.2768x over previous
#include <cuda_runtime.h>
#include <math.h>

// CTC batch cost (keras.backend.ctc_batch_cost, full lengths, blank=C-1).
// Forward/backward split: warp pair per batch row. Forward warp computes
// alpha_255 (steps 1..255, chunks 0..31); backward warp computes beta_255
// (steps 511..256, chunks 63..32). loss = -log(sum_s alpha*beta).
// Linear space, per-lane power-of-2 renorm (exact), cp.async smem ring.
//
// y_true [B=512, L=64] int32, y_pred [B=512, T=512, C=96] f32, out [B,1] f32.

constexpr int T_DIM = 512;
constexpr int C_DIM = 96;
constexpr int L_DIM = 64;
constexpr int S_DIM = 2 * L_DIM + 1;   // 129
constexpr int BLANK = C_DIM - 1;       // 95
constexpr int KPL   = 5;
constexpr int CH    = 8;               // t-rows per chunk
constexpr int STG   = 4;               // smem ring stages per warp
constexpr int NCH   = 32;              // chunks per direction
constexpr int ROWS_PB = 4;             // batch rows per block (8 warps)
constexpr float EPSF = 1e-7f;

constexpr int RING_F = 8 * STG * (CH * C_DIM);          // ring floats
constexpr int SMEM_BYTES = RING_F * 4 + ROWS_PB*32*KPL*4 + ROWS_PB*32*4;

#define FULLMASK 0xffffffffu

__global__ void __launch_bounds__(256, 1)
ctc_fb_kernel(const int* __restrict__ y_true,
              const float* __restrict__ y_pred,
              float* __restrict__ out, int B)
{
    extern __shared__ float smem[];
    float* ring = smem;                                   // [8][STG][768]
    float* resB = ring + RING_F;                          // [4][32][KPL]
    int*   resE = (int*)(resB + ROWS_PB * 32 * KPL);      // [4][32]

    const int tid  = threadIdx.x;
    const int warp = tid >> 5, lane = tid & 31;
    const int rowi = warp >> 1, dir = warp & 1;           // 0=fwd, 1=bwd
    int b = blockIdx.x * ROWS_PB + rowi;
    if (b >= B) b = B - 1;                                // benign duplicate

    const float* __restrict__ P = y_pred + (size_t)b * (size_t)(T_DIM * C_DIM);
    const int* __restrict__ lab = y_true + (size_t)b * L_DIM;

    // Static per-state info. State s = lane*KPL + k.
    // fwd: skA[k] = skip(s);  bwd: skA[k] = skip(s+2)  (dest-state skip flag)
    int cls[KPL];
    float skA[KPL];
#pragma unroll
    for (int k = 0; k < KPL; ++k) {
        int s = lane * KPL + k;
        int c = BLANK;
        if (s < S_DIM && (s & 1)) {
            int j = (s - 1) >> 1;
            c = lab[j];
            c = max(0, min(C_DIM - 1, c));
        }
        cls[k] = c;
        int sq = dir ? s + 2 : s;
        float sk = 0.f;
        if (sq >= 3 && sq < S_DIM && (sq & 1)) {
            int j = (sq - 1) >> 1;
            if (lab[j] != lab[j - 1]) sk = 1.f;
        }
        skA[k] = sk;
    }

    // state vector (alpha for fwd, beta for bwd); true value = a[k] * 2^E
    float a[KPL];
#pragma unroll
    for (int k = 0; k < KPL; ++k) a[k] = 0.f;
    if (dir == 0) {
        if (lane == 0) { a[0] = P[cls[0]] + EPSF; a[1] = P[cls[1]] + EPSF; }
    } else {
        if (lane == 25) { a[2] = 1.f; a[3] = 1.f; }   // states 127, 128
    }
    int   E = 0;
    float f = 1.f;

    float* wring = ring + warp * STG * (CH * C_DIM);

    // producer: coalesced cp.async of one 8-row chunk (3072 B)
    auto issue = [&](int i) {                 // i = 0..31 (warp-local order)
        int c = dir ? (2 * NCH - 1 - i) : i;  // global chunk id
        const float4* g = (const float4*)(P + (size_t)c * (CH * C_DIM));
        unsigned sa = (unsigned)__cvta_generic_to_shared(
            wring + (i & (STG - 1)) * (CH * C_DIM));
#pragma unroll
        for (int j = 0; j < 6; ++j) {
            int idx = lane + 32 * j;
            asm volatile("cp.async.cg.shared.global [%0], [%1], 16;\n"
                         :: "r"(sa + idx * 16), "l"(g + idx));
        }
        asm volatile("cp.async.commit_group;\n" ::: "memory");
    };

    auto ldp = [&](int t, float (&pp)[KPL]) {
        int c = t >> 3;
        int i = dir ? (2 * NCH - 1 - c) : c;
        const float* rb = wring + (i & (STG - 1)) * (CH * C_DIM)
                        + (t & (CH - 1)) * C_DIM;
#pragma unroll
        for (int k = 0; k < KPL; ++k) pp[k] = rb[cls[k]];
    };

    auto step_fwd = [&](const float (&p)[KPL]) {
        float am1 = __shfl_up_sync(FULLMASK, a[KPL - 1], 1);
        float am2 = __shfl_up_sync(FULLMASK, a[KPL - 2], 1);
        if (lane == 0) { am1 = 0.f; am2 = 0.f; }
        am1 *= f; am2 *= f;
        float q0 = p[0]+EPSF, q1 = p[1]+EPSF, q2 = p[2]+EPSF,
              q3 = p[3]+EPSF, q4 = p[4]+EPSF;
        float n0 = fmaf(skA[0], am2,  a[0] + am1)  * q0;
        float n1 = fmaf(skA[1], am1,  a[1] + a[0]) * q1;
        float n2 = fmaf(skA[2], a[0], a[2] + a[1]) * q2;
        float n3 = fmaf(skA[3], a[1], a[3] + a[2]) * q3;
        float n4 = fmaf(skA[4], a[2], a[4] + a[3]) * q4;
        a[0]=n0; a[1]=n1; a[2]=n2; a[3]=n3; a[4]=n4;
    };

    auto step_bwd = [&](const float (&p)[KPL]) {
        float g0 = (p[0]+EPSF)*a[0], g1 = (p[1]+EPSF)*a[1],
              g2 = (p[2]+EPSF)*a[2], g3 = (p[3]+EPSF)*a[3],
              g4 = (p[4]+EPSF)*a[4];
        float gp0 = __shfl_down_sync(FULLMASK, g0, 1);
        float gp1 = __shfl_down_sync(FULLMASK, g1, 1);
        if (lane == 31) { gp0 = 0.f; gp1 = 0.f; }
        gp0 *= f; gp1 *= f;
        float n0 = fmaf(skA[0], g2,  g0 + g1);
        float n1 = fmaf(skA[1], g3,  g1 + g2);
        float n2 = fmaf(skA[2], g4,  g2 + g3);
        float n3 = fmaf(skA[3], gp0, g3 + g4);
        float n4 = fmaf(skA[4], gp1, g4 + gp0);
        a[0]=n0; a[1]=n1; a[2]=n2; a[3]=n3; a[4]=n4;
    };

    auto renorm = [&]() {
        float m = fmaxf(fmaxf(fmaxf(a[0], a[1]), fmaxf(a[2], a[3])), a[4]);
        bool ne = (m > 0.f);
        if (ne) {
            int mb = __float_as_int(m) >> 23;
            if (mb == 0) {                           // denormal max: boost
                const float up = 0x1p126f;
#pragma unroll
                for (int k = 0; k < KPL; ++k) a[k] *= up;
                E -= 126;
                m *= up;
                mb = __float_as_int(m) >> 23;
            }
            float scale = __int_as_float((254 - mb) << 23);   // exact 2^{-e}
#pragma unroll
            for (int k = 0; k < KPL; ++k) a[k] *= scale;
            E += mb - 127;
        }
        unsigned bm = __ballot_sync(FULLMASK, ne);
        if (dir == 0) {          // mass flows low->high lanes
            unsigned below = bm & ((2u << lane) - 1u);
            int src = below ? (31 - __clz(below)) : lane;
            int Ead = __shfl_sync(FULLMASK, E, src);
            if (!ne) E = Ead;
            int Ep = __shfl_up_sync(FULLMASK, E, 1);
            int d = (lane == 0) ? 0 : (Ep - E);
            d = max(-127, min(120, d));
            f = (d <= -127) ? 0.f : __int_as_float((d + 127) << 23);
        } else {                 // mass flows high->low lanes
            unsigned up = bm & ~((1u << lane) - 1u);
            int src = up ? (__ffs(up) - 1) : lane;
            int Ead = __shfl_sync(FULLMASK, E, src);
            if (!ne) E = Ead;
            int Ep = __shfl_down_sync(FULLMASK, E, 1);
            int d = (lane == 31) ? 0 : (Ep - E);
            d = max(-127, min(120, d));
            f = (d <= -127) ? 0.f : __int_as_float((d + 127) << 23);
        }
    };

    // ---- pipeline ----
    issue(0); issue(1); issue(2);
    float pc[KPL];
#pragma unroll 1
    for (int i = 0; i < NCH; ++i) {
        if (i + 3 < NCH) issue(i + 3);
        if (i < NCH - 3)
            asm volatile("cp.async.wait_group 2;\n" ::: "memory");
        else
            asm volatile("cp.async.wait_group 0;\n" ::: "memory");
        __syncwarp();

        if (dir == 0) {
            if (i == 0) ldp(1, pc);
#pragma unroll
            for (int j = 0; j < CH; ++j) {
                int t = i * CH + j;
                if (t == 0) continue;
                float pn[KPL];
                int tn = (t + 1 < 256) ? t + 1 : 255;
                ldp(tn, pn);
                step_fwd(pc);
#pragma unroll
                for (int k = 0; k < KPL; ++k) pc[k] = pn[k];
            }
        } else {
            if (i == 0) ldp(T_DIM - 1, pc);
#pragma unroll
            for (int j = 0; j < CH; ++j) {
                int t = (2 * NCH - 1 - i) * CH + (CH - 1 - j);  // 511-(i*8+j)
                float pn[KPL];
                int tn = (t - 1 > 256) ? t - 1 : 256;
                ldp(tn, pn);
                step_bwd(pc);
#pragma unroll
                for (int k = 0; k < KPL; ++k) pc[k] = pn[k];
            }
        }
        renorm();
    }

    // ---- combine: loss = -log( sum_s alpha_255(s) * beta_255(s) ) ----
    if (dir == 1) {
#pragma unroll
        for (int k = 0; k < KPL; ++k)
            resB[(rowi * 32 + lane) * KPL + k] = a[k];
        resE[rowi * 32 + lane] = E;
    }
    __syncthreads();
    if (dir == 0) {
        double sd = 0.0;
#pragma unroll
        for (int k = 0; k < KPL; ++k)
            sd += (double)a[k] * (double)resB[(rowi * 32 + lane) * KPL + k];
        int X = E + resE[rowi * 32 + lane];
        bool valid = (sd > 0.0);
        int es = valid ? ilogb(sd) : 0;
        int key = valid ? (X + es) : -1000000000;
        int M = key;
#pragma unroll
        for (int o = 16; o > 0; o >>= 1)
            M = max(M, __shfl_xor_sync(FULLMASK, M, o));
        float term = 0.f;
        if (valid) {
            double mant = scalbn(sd, -es);     // in [1,2)
            int d = key - M;
            if (d >= -126) term = (float)mant * __int_as_float((d + 127) << 23);
        }
#pragma unroll
        for (int o = 16; o > 0; o >>= 1)
            term += __shfl_xor_sync(FULLMASK, term, o);
        if (lane == 0)
            out[b] = (float)(-(log((double)term)
                              + (double)M * 0.6931471805599453));
    }
}

extern "C" void kernel_launch(void* const* d_in, const int* in_sizes, int n_in,
                              void* d_out, int out_size)
{
    int iy = 0, ip = 1;
    if (n_in >= 2 && in_sizes[0] > in_sizes[1]) { iy = 1; ip = 0; }
    const int* y_true = (const int*)d_in[iy];
    const float* y_pred = (const float*)d_in[ip];
    float* out = (float*)d_out;
    int B = in_sizes[iy] / L_DIM;                 // 512
    static bool configured = false;
    if (!configured) {
        cudaFuncSetAttribute(ctc_fb_kernel,
                             cudaFuncAttributeMaxDynamicSharedMemorySize,
                             SMEM_BYTES);
        configured = true;
    }
    int grid = (B + ROWS_PB - 1) / ROWS_PB;       // 128
    ctc_fb_kernel<<<grid, 256, SMEM_BYTES>>>(y_true, y_pred, out, B);
}

// round 11
// speedup vs baseline: 6.5018x; 1.0920x over previous
#include <cuda_runtime.h>
#include <math.h>

// CTC batch cost (keras.backend.ctc_batch_cost, full lengths, blank=C-1).
// Forward/backward split: warp pair per batch row; fwd computes alpha_255
// (t=1..255), bwd computes beta_255 (t=511..256); loss = -log(sum alpha*beta).
// Linear space, per-lane power-of-2 renorm every 16 steps (exact scaling),
// cp.async smem ring, per-chunk pointer precompute (no per-step addr math).
//
// y_true [B=512, L=64] int32, y_pred [B=512, T=512, C=96] f32, out [B,1] f32.

constexpr int T_DIM = 512;
constexpr int C_DIM = 96;
constexpr int L_DIM = 64;
constexpr int S_DIM = 2 * L_DIM + 1;   // 129
constexpr int BLANK = C_DIM - 1;       // 95
constexpr int KPL   = 5;
constexpr int CH    = 8;               // t-rows per chunk
constexpr int STG   = 4;               // smem ring stages per warp
constexpr int NCH   = 32;              // chunks per direction
constexpr int ROWS_PB = 4;             // batch rows per block (8 warps)
constexpr float EPSF = 1e-7f;

constexpr int RING_F = 8 * STG * (CH * C_DIM);          // ring floats
constexpr int SMEM_BYTES = RING_F * 4 + ROWS_PB*32*KPL*4 + ROWS_PB*32*4;

#define FULLMASK 0xffffffffu

__global__ void __launch_bounds__(256, 1)
ctc_fb_kernel(const int* __restrict__ y_true,
              const float* __restrict__ y_pred,
              float* __restrict__ out, int B)
{
    extern __shared__ float smem[];
    float* ring = smem;                                   // [8][STG][768]
    float* resB = ring + RING_F;                          // [4][32][KPL]
    int*   resE = (int*)(resB + ROWS_PB * 32 * KPL);      // [4][32]

    const int tid  = threadIdx.x;
    const int warp = tid >> 5, lane = tid & 31;
    const int rowi = warp >> 1, dir = warp & 1;           // 0=fwd, 1=bwd
    const int b = blockIdx.x * ROWS_PB + rowi;

    const float* __restrict__ P = y_pred + (size_t)b * (size_t)(T_DIM * C_DIM);
    const int* __restrict__ lab = y_true + (size_t)b * L_DIM;

    // Static per-state info. State s = lane*KPL + k.
    // fwd: skA[k] = skip(s);  bwd: skA[k] = skip(s+2)  (dest-state flag)
    int cls[KPL];
    float skA[KPL];
#pragma unroll
    for (int k = 0; k < KPL; ++k) {
        int s = lane * KPL + k;
        int c = BLANK;
        if (s < S_DIM && (s & 1)) {
            int j = (s - 1) >> 1;
            c = lab[j];
            c = max(0, min(C_DIM - 1, c));
        }
        cls[k] = c;
        int sq = dir ? s + 2 : s;
        float sk = 0.f;
        if (sq >= 3 && sq < S_DIM && (sq & 1)) {
            int j = (sq - 1) >> 1;
            if (lab[j] != lab[j - 1]) sk = 1.f;
        }
        skA[k] = sk;
    }

    // state vector (alpha fwd / beta bwd); true value = a[k] * 2^E
    float a[KPL];
#pragma unroll
    for (int k = 0; k < KPL; ++k) a[k] = 0.f;
    if (dir == 0) {
        if (lane == 0) { a[0] = P[cls[0]] + EPSF; a[1] = P[cls[1]] + EPSF; }
    } else {
        if (lane == 25) { a[2] = 1.f; a[3] = 1.f; }   // states 127, 128
    }
    int   E = 0;
    float f = 1.f;

    float* wring = ring + warp * STG * (CH * C_DIM);

    // producer: coalesced cp.async of one 8-row chunk (3072 B)
    auto issue = [&](int i) {                 // i = 0..31 (warp-local order)
        int c = dir ? (2 * NCH - 1 - i) : i;  // global chunk id
        const float4* g = (const float4*)(P + (size_t)c * (CH * C_DIM));
        unsigned sa = (unsigned)__cvta_generic_to_shared(
            wring + (i & (STG - 1)) * (CH * C_DIM));
#pragma unroll
        for (int j = 0; j < 6; ++j) {
            int idx = lane + 32 * j;
            asm volatile("cp.async.cg.shared.global [%0], [%1], 16;\n"
                         :: "r"(sa + idx * 16), "l"(g + idx));
        }
        asm volatile("cp.async.commit_group;\n" ::: "memory");
    };

    auto step_fwd = [&](float q0, float q1, float q2, float q3, float q4) {
        float am1 = __shfl_up_sync(FULLMASK, a[4], 1);
        float am2 = __shfl_up_sync(FULLMASK, a[3], 1);
        if (lane == 0) { am1 = 0.f; am2 = 0.f; }
        am1 *= f; am2 *= f;
        float n0 = fmaf(skA[0], am2,  a[0] + am1)  * q0;
        float n1 = fmaf(skA[1], am1,  a[1] + a[0]) * q1;
        float n2 = fmaf(skA[2], a[0], a[2] + a[1]) * q2;
        float n3 = fmaf(skA[3], a[1], a[3] + a[2]) * q3;
        float n4 = fmaf(skA[4], a[2], a[4] + a[3]) * q4;
        a[0]=n0; a[1]=n1; a[2]=n2; a[3]=n3; a[4]=n4;
    };

    auto step_bwd = [&](float q0, float q1, float q2, float q3, float q4) {
        float g0 = q0*a[0], g1 = q1*a[1], g2 = q2*a[2],
              g3 = q3*a[3], g4 = q4*a[4];
        float gp0 = __shfl_down_sync(FULLMASK, g0, 1);
        float gp1 = __shfl_down_sync(FULLMASK, g1, 1);
        if (lane == 31) { gp0 = 0.f; gp1 = 0.f; }
        gp0 *= f; gp1 *= f;
        float n0 = fmaf(skA[0], g2,  g0 + g1);
        float n1 = fmaf(skA[1], g3,  g1 + g2);
        float n2 = fmaf(skA[2], g4,  g2 + g3);
        float n3 = fmaf(skA[3], gp0, g3 + g4);
        float n4 = fmaf(skA[4], gp1, g4 + gp0);
        a[0]=n0; a[1]=n1; a[2]=n2; a[3]=n3; a[4]=n4;
    };

    auto renorm = [&]() {
        float m = fmaxf(fmaxf(fmaxf(a[0], a[1]), fmaxf(a[2], a[3])), a[4]);
        bool ne = (m > 0.f);
        if (ne) {
            int mb = __float_as_int(m) >> 23;
            if (mb == 0) {                           // denormal max: boost
                const float up = 0x1p126f;
#pragma unroll
                for (int k = 0; k < KPL; ++k) a[k] *= up;
                E -= 126;
                m *= up;
                mb = __float_as_int(m) >> 23;
            }
            float scale = __int_as_float((254 - mb) << 23);   // exact 2^{-e}
#pragma unroll
            for (int k = 0; k < KPL; ++k) a[k] *= scale;
            E += mb - 127;
        }
        unsigned bm = __ballot_sync(FULLMASK, ne);
        if (dir == 0) {          // mass flows low->high lanes
            unsigned below = bm & ((2u << lane) - 1u);
            int src = below ? (31 - __clz(below)) : lane;
            int Ead = __shfl_sync(FULLMASK, E, src);
            if (!ne) E = Ead;
            int Ep = __shfl_up_sync(FULLMASK, E, 1);
            int d = (lane == 0) ? 0 : (Ep - E);
            d = max(-127, min(120, d));
            f = (d <= -127) ? 0.f : __int_as_float((d + 127) << 23);
        } else {                 // mass flows high->low lanes
            unsigned up = bm & ~((1u << lane) - 1u);
            int src = up ? (__ffs(up) - 1) : lane;
            int Ead = __shfl_sync(FULLMASK, E, src);
            if (!ne) E = Ead;
            int Ep = __shfl_down_sync(FULLMASK, E, 1);
            int d = (lane == 31) ? 0 : (Ep - E);
            d = max(-127, min(120, d));
            f = (d <= -127) ? 0.f : __int_as_float((d + 127) << 23);
        }
    };

    // ---- pipeline ----
    issue(0); issue(1); issue(2);
#pragma unroll 1
    for (int i = 0; i < NCH; ++i) {
        if (i + 3 < NCH) issue(i + 3);
        if (i < NCH - 3)
            asm volatile("cp.async.wait_group 2;\n" ::: "memory");
        else
            asm volatile("cp.async.wait_group 0;\n" ::: "memory");
        __syncwarp();

        // per-chunk gather bases: row offset folds into the LDS immediate
        const float* sb = wring + (i & (STG - 1)) * (CH * C_DIM);
        const float* b0 = sb + cls[0];
        const float* b1 = sb + cls[1];
        const float* b2 = sb + cls[2];
        const float* b3 = sb + cls[3];
        const float* b4 = sb + cls[4];

        if (dir == 0) {
            if (i == 0) {
#pragma unroll
                for (int j = 1; j < CH; ++j)
                    step_fwd(b0[j*C_DIM]+EPSF, b1[j*C_DIM]+EPSF,
                             b2[j*C_DIM]+EPSF, b3[j*C_DIM]+EPSF,
                             b4[j*C_DIM]+EPSF);
            } else {
#pragma unroll
                for (int j = 0; j < CH; ++j)
                    step_fwd(b0[j*C_DIM]+EPSF, b1[j*C_DIM]+EPSF,
                             b2[j*C_DIM]+EPSF, b3[j*C_DIM]+EPSF,
                             b4[j*C_DIM]+EPSF);
            }
        } else {
#pragma unroll
            for (int j = 0; j < CH; ++j) {
                int r = CH - 1 - j;     // t = 511 - (i*8 + j)
                step_bwd(b0[r*C_DIM]+EPSF, b1[r*C_DIM]+EPSF,
                         b2[r*C_DIM]+EPSF, b3[r*C_DIM]+EPSF,
                         b4[r*C_DIM]+EPSF);
            }
        }
        if (i & 1) renorm();            // every 16 steps
    }

    // ---- combine: loss = -log( sum_s alpha_255(s) * beta_255(s) ) ----
    if (dir == 1) {
#pragma unroll
        for (int k = 0; k < KPL; ++k)
            resB[(rowi * 32 + lane) * KPL + k] = a[k];
        resE[rowi * 32 + lane] = E;
    }
    __syncthreads();
    if (dir == 0) {
        double sd = 0.0;
#pragma unroll
        for (int k = 0; k < KPL; ++k)
            sd += (double)a[k] * (double)resB[(rowi * 32 + lane) * KPL + k];
        int X = E + resE[rowi * 32 + lane];
        bool valid = (sd > 0.0);
        int es = valid ? ilogb(sd) : 0;
        int key = valid ? (X + es) : -1000000000;
        int M = key;
#pragma unroll
        for (int o = 16; o > 0; o >>= 1)
            M = max(M, __shfl_xor_sync(FULLMASK, M, o));
        float term = 0.f;
        if (valid) {
            double mant = scalbn(sd, -es);     // in [1,2)
            int d = key - M;
            if (d >= -126) term = (float)mant * __int_as_float((d + 127) << 23);
        }
#pragma unroll
        for (int o = 16; o > 0; o >>= 1)
            term += __shfl_xor_sync(FULLMASK, term, o);
        if (lane == 0)
            out[b] = (float)(-(log((double)term)
                              + (double)M * 0.6931471805599453));
    }
}

extern "C" void kernel_launch(void* const* d_in, const int* in_sizes, int n_in,
                              void* d_out, int out_size)
{
    int iy = 0, ip = 1;
    if (n_in >= 2 && in_sizes[0] > in_sizes[1]) { iy = 1; ip = 0; }
    const int* y_true = (const int*)d_in[iy];
    const float* y_pred = (const float*)d_in[ip];
    float* out = (float*)d_out;
    int B = in_sizes[iy] / L_DIM;                 // 512
    static bool configured = false;
    if (!configured) {
        cudaFuncSetAttribute(ctc_fb_kernel,
                             cudaFuncAttributeMaxDynamicSharedMemorySize,
                             SMEM_BYTES);
        configured = true;
    }
    int grid = (B + ROWS_PB - 1) / ROWS_PB;       // 128
    ctc_fb_kernel<<<grid, 256, SMEM_BYTES>>>(y_true, y_pred, out, B);
}

// round 12
// speedup vs baseline: 6.8712x; 1.0568x over previous
#include <cuda_runtime.h>
#include <math.h>

// CTC batch cost (keras.backend.ctc_batch_cost, full lengths, blank=C-1).
// Forward/backward split: warp pair per batch row; fwd computes alpha_255
// (t=1..255), bwd computes beta_255 (t=511..256); loss = -log(sum alpha*beta).
// Linear space, per-lane power-of-2 renorm every 16 steps (exact scaling),
// cp.async smem ring (16-row chunks, 4 stages), boundary lanes handled by
// per-lane f=0 (no selects in the hot loop).
//
// y_true [B=512, L=64] int32, y_pred [B=512, T=512, C=96] f32, out [B,1] f32.

constexpr int T_DIM = 512;
constexpr int C_DIM = 96;
constexpr int L_DIM = 64;
constexpr int S_DIM = 2 * L_DIM + 1;   // 129
constexpr int BLANK = C_DIM - 1;       // 95
constexpr int KPL   = 5;
constexpr int CH    = 16;              // t-rows per chunk
constexpr int STG   = 4;               // smem ring stages per warp
constexpr int NCH   = 16;              // chunks per direction (256/16)
constexpr int NCHG  = 32;              // global chunks (512/16)
constexpr int ROWS_PB = 4;             // batch rows per block (8 warps)
constexpr float EPSF = 1e-7f;

constexpr int CHF    = CH * C_DIM;                       // 1536 floats/chunk
constexpr int RING_F = 8 * STG * CHF;                    // 49152 floats
constexpr int SMEM_BYTES = RING_F * 4 + ROWS_PB*32*KPL*4 + ROWS_PB*32*4;

#define FULLMASK 0xffffffffu

__global__ void __launch_bounds__(256, 1)
ctc_fb_kernel(const int* __restrict__ y_true,
              const float* __restrict__ y_pred,
              float* __restrict__ out, int B)
{
    extern __shared__ float smem[];
    float* ring = smem;                                   // [8][STG][1536]
    float* resB = ring + RING_F;                          // [4][32][KPL]
    int*   resE = (int*)(resB + ROWS_PB * 32 * KPL);      // [4][32]

    const int tid  = threadIdx.x;
    const int warp = tid >> 5, lane = tid & 31;
    const int rowi = warp >> 1, dir = warp & 1;           // 0=fwd, 1=bwd
    const int b = blockIdx.x * ROWS_PB + rowi;

    const float* __restrict__ P = y_pred + (size_t)b * (size_t)(T_DIM * C_DIM);
    const int* __restrict__ lab = y_true + (size_t)b * L_DIM;

    // Static per-state info. State s = lane*KPL + k.
    // fwd: skA[k] = skip(s);  bwd: skA[k] = skip(s+2)  (dest-state flag)
    int cls[KPL];
    float skA[KPL];
#pragma unroll
    for (int k = 0; k < KPL; ++k) {
        int s = lane * KPL + k;
        int c = BLANK;
        if (s < S_DIM && (s & 1)) {
            int j = (s - 1) >> 1;
            c = lab[j];
            c = max(0, min(C_DIM - 1, c));
        }
        cls[k] = c;
        int sq = dir ? s + 2 : s;
        float sk = 0.f;
        if (sq >= 3 && sq < S_DIM && (sq & 1)) {
            int j = (sq - 1) >> 1;
            if (lab[j] != lab[j - 1]) sk = 1.f;
        }
        skA[k] = sk;
    }

    // state vector (alpha fwd / beta bwd); true value = a[k] * 2^E
    float a[KPL];
#pragma unroll
    for (int k = 0; k < KPL; ++k) a[k] = 0.f;
    if (dir == 0) {
        if (lane == 0) { a[0] = P[cls[0]] + EPSF; a[1] = P[cls[1]] + EPSF; }
    } else {
        if (lane == 25) { a[2] = 1.f; a[3] = 1.f; }   // states 127, 128
    }
    int E = 0;
    // boundary lanes carry f=0 forever: shfl returns own value there, *0 = 0.
    const bool bnd = (dir == 0) ? (lane == 0) : (lane == 31);
    float f = bnd ? 0.f : 1.f;

    float* wring = ring + warp * STG * CHF;

    // producer: coalesced cp.async of one 16-row chunk (6144 B)
    auto issue = [&](int i) {                 // i = 0..15 (warp-local order)
        int c = dir ? (NCHG - 1 - i) : i;     // global chunk id
        const float4* g = (const float4*)(P + (size_t)c * CHF);
        unsigned sa = (unsigned)__cvta_generic_to_shared(
            wring + (i & (STG - 1)) * CHF);
#pragma unroll
        for (int j = 0; j < 12; ++j) {        // 384 float4 / 32 lanes
            int idx = lane + 32 * j;
            asm volatile("cp.async.cg.shared.global [%0], [%1], 16;\n"
                         :: "r"(sa + idx * 16), "l"(g + idx));
        }
        asm volatile("cp.async.commit_group;\n" ::: "memory");
    };

    auto step_fwd = [&](float q0, float q1, float q2, float q3, float q4) {
        float am1 = __shfl_up_sync(FULLMASK, a[4], 1) * f;
        float am2 = __shfl_up_sync(FULLMASK, a[3], 1) * f;
        float n0 = fmaf(skA[0], am2,  a[0] + am1)  * q0;
        float n1 = fmaf(skA[1], am1,  a[1] + a[0]) * q1;
        float n2 = fmaf(skA[2], a[0], a[2] + a[1]) * q2;
        float n3 = fmaf(skA[3], a[1], a[3] + a[2]) * q3;
        float n4 = fmaf(skA[4], a[2], a[4] + a[3]) * q4;
        a[0]=n0; a[1]=n1; a[2]=n2; a[3]=n3; a[4]=n4;
    };

    auto step_bwd = [&](float q0, float q1, float q2, float q3, float q4) {
        float g0 = q0*a[0], g1 = q1*a[1], g2 = q2*a[2],
              g3 = q3*a[3], g4 = q4*a[4];
        float gp0 = __shfl_down_sync(FULLMASK, g0, 1) * f;
        float gp1 = __shfl_down_sync(FULLMASK, g1, 1) * f;
        float n0 = fmaf(skA[0], g2,  g0 + g1);
        float n1 = fmaf(skA[1], g3,  g1 + g2);
        float n2 = fmaf(skA[2], g4,  g2 + g3);
        float n3 = fmaf(skA[3], gp0, g3 + g4);
        float n4 = fmaf(skA[4], gp1, g4 + gp0);
        a[0]=n0; a[1]=n1; a[2]=n2; a[3]=n3; a[4]=n4;
    };

    auto renorm = [&]() {
        float m = fmaxf(fmaxf(fmaxf(a[0], a[1]), fmaxf(a[2], a[3])), a[4]);
        bool ne = (m > 0.f);
        if (ne) {
            int mb = __float_as_int(m) >> 23;
            if (mb == 0) {                           // denormal max: boost
                const float up = 0x1p126f;
#pragma unroll
                for (int k = 0; k < KPL; ++k) a[k] *= up;
                E -= 126;
                m *= up;
                mb = __float_as_int(m) >> 23;
            }
            float scale = __int_as_float((254 - mb) << 23);   // exact 2^{-e}
#pragma unroll
            for (int k = 0; k < KPL; ++k) a[k] *= scale;
            E += mb - 127;
        }
        unsigned bm = __ballot_sync(FULLMASK, ne);
        if (dir == 0) {          // mass flows low->high lanes
            unsigned below = bm & ((2u << lane) - 1u);
            int src = below ? (31 - __clz(below)) : lane;
            int Ead = __shfl_sync(FULLMASK, E, src);
            if (!ne) E = Ead;
            int Ep = __shfl_up_sync(FULLMASK, E, 1);
            int d = Ep - E;
            d = max(-127, min(120, d));
            f = (bnd || d <= -127) ? 0.f : __int_as_float((d + 127) << 23);
        } else {                 // mass flows high->low lanes
            unsigned up = bm & ~((1u << lane) - 1u);
            int src = up ? (__ffs(up) - 1) : lane;
            int Ead = __shfl_sync(FULLMASK, E, src);
            if (!ne) E = Ead;
            int Ep = __shfl_down_sync(FULLMASK, E, 1);
            int d = Ep - E;
            d = max(-127, min(120, d));
            f = (bnd || d <= -127) ? 0.f : __int_as_float((d + 127) << 23);
        }
    };

    // ---- pipeline: depth-3 prologue ----
    issue(0); issue(1); issue(2);
#pragma unroll 1
    for (int i = 0; i < NCH; ++i) {
        if (i + 3 < NCH) issue(i + 3);
        if (i < NCH - 3)
            asm volatile("cp.async.wait_group 3;\n" ::: "memory");
        else
            asm volatile("cp.async.wait_group 0;\n" ::: "memory");
        __syncwarp();

        // per-chunk gather bases: row offset folds into the LDS immediate
        const float* sb = wring + (i & (STG - 1)) * CHF;
        const float* b0 = sb + cls[0];
        const float* b1 = sb + cls[1];
        const float* b2 = sb + cls[2];
        const float* b3 = sb + cls[3];
        const float* b4 = sb + cls[4];

        if (dir == 0) {
            if (i == 0) {
#pragma unroll
                for (int j = 1; j < CH; ++j)
                    step_fwd(b0[j*C_DIM]+EPSF, b1[j*C_DIM]+EPSF,
                             b2[j*C_DIM]+EPSF, b3[j*C_DIM]+EPSF,
                             b4[j*C_DIM]+EPSF);
            } else {
#pragma unroll
                for (int j = 0; j < CH; ++j)
                    step_fwd(b0[j*C_DIM]+EPSF, b1[j*C_DIM]+EPSF,
                             b2[j*C_DIM]+EPSF, b3[j*C_DIM]+EPSF,
                             b4[j*C_DIM]+EPSF);
            }
        } else {
#pragma unroll
            for (int j = 0; j < CH; ++j) {
                int r = CH - 1 - j;     // t = 511 - (i*16 + j)
                step_bwd(b0[r*C_DIM]+EPSF, b1[r*C_DIM]+EPSF,
                         b2[r*C_DIM]+EPSF, b3[r*C_DIM]+EPSF,
                         b4[r*C_DIM]+EPSF);
            }
        }
        renorm();                       // every 16 steps
    }

    // ---- combine: loss = -log( sum_s alpha_255(s) * beta_255(s) ) ----
    if (dir == 1) {
#pragma unroll
        for (int k = 0; k < KPL; ++k)
            resB[(rowi * 32 + lane) * KPL + k] = a[k];
        resE[rowi * 32 + lane] = E;
    }
    __syncthreads();
    if (dir == 0) {
        double sd = 0.0;
#pragma unroll
        for (int k = 0; k < KPL; ++k)
            sd += (double)a[k] * (double)resB[(rowi * 32 + lane) * KPL + k];
        int X = E + resE[rowi * 32 + lane];
        bool valid = (sd > 0.0);
        int es = valid ? ilogb(sd) : 0;
        int key = valid ? (X + es) : -1000000000;
        int M = key;
#pragma unroll
        for (int o = 16; o > 0; o >>= 1)
            M = max(M, __shfl_xor_sync(FULLMASK, M, o));
        float term = 0.f;
        if (valid) {
            double mant = scalbn(sd, -es);     // in [1,2)
            int d = key - M;
            if (d >= -126) term = (float)mant * __int_as_float((d + 127) << 23);
        }
#pragma unroll
        for (int o = 16; o > 0; o >>= 1)
            term += __shfl_xor_sync(FULLMASK, term, o);
        if (lane == 0)
            out[b] = (float)(-(log((double)term)
                              + (double)M * 0.6931471805599453));
    }
}

extern "C" void kernel_launch(void* const* d_in, const int* in_sizes, int n_in,
                              void* d_out, int out_size)
{
    int iy = 0, ip = 1;
    if (n_in >= 2 && in_sizes[0] > in_sizes[1]) { iy = 1; ip = 0; }
    const int* y_true = (const int*)d_in[iy];
    const float* y_pred = (const float*)d_in[ip];
    float* out = (float*)d_out;
    int B = in_sizes[iy] / L_DIM;                 // 512
    static bool configured = false;
    if (!configured) {
        cudaFuncSetAttribute(ctc_fb_kernel,
                             cudaFuncAttributeMaxDynamicSharedMemorySize,
                             SMEM_BYTES);
        configured = true;
    }
    int grid = (B + ROWS_PB - 1) / ROWS_PB;       // 128
    ctc_fb_kernel<<<grid, 256, SMEM_BYTES>>>(y_true, y_pred, out, B);
}

// round 15
// speedup vs baseline: 7.4753x; 1.0879x over previous
#include <cuda_runtime.h>
#include <math.h>

// CTC batch cost (keras.backend.ctc_batch_cost, full lengths, blank=C-1).
// Forward/backward split: warp pair per batch row; fwd computes alpha_255
// (t=1..255), bwd computes beta_255 (t=511..256); loss = -log(sum alpha*beta).
// Linear space, per-lane power-of-2 renorm every 8 steps (exact scaling;
// 8-step cadence bounds the inter-renorm cross-lane growth cascade well
// below fp32 overflow). KPL=4 parity mapping: state s = 4*lane + k; slots
// 0,2 blank (one broadcast LDS), slots 1,3 labels; state 128 is the
// warp-uniform scalar 'atop' carried in lane 31's scale.
//
// y_true [B=512, L=64] int32, y_pred [B=512, T=512, C=96] f32, out [B,1] f32.

constexpr int T_DIM = 512;
constexpr int C_DIM = 96;
constexpr int L_DIM = 64;
constexpr int BLANK = C_DIM - 1;       // 95
constexpr int CH    = 16;              // t-rows per chunk
constexpr int STG   = 4;               // smem ring stages per warp
constexpr int NCH   = 16;              // chunks per direction (256/16)
constexpr int NCHG  = 32;              // global chunks (512/16)
constexpr int ROWS_PB = 4;             // batch rows per block (8 warps)
constexpr float EPSF = 1e-7f;

constexpr int CHF    = CH * C_DIM;                       // 1536 floats/chunk
constexpr int RING_F = 8 * STG * CHF;                    // 49152 floats
constexpr int SMEM_BYTES = RING_F * 4 + ROWS_PB*32*5*4 + ROWS_PB*32*4;

#define FULLMASK 0xffffffffu

__global__ void __launch_bounds__(256, 1)
ctc_fb_kernel(const int* __restrict__ y_true,
              const float* __restrict__ y_pred,
              float* __restrict__ out, int B)
{
    extern __shared__ float smem[];
    float* ring = smem;                                   // [8][STG][1536]
    float* resB = ring + RING_F;                          // [4][32][5]
    int*   resE = (int*)(resB + ROWS_PB * 32 * 5);        // [4][32]

    const int tid  = threadIdx.x;
    const int warp = tid >> 5, lane = tid & 31;
    const int rowi = warp >> 1, dir = warp & 1;           // 0=fwd, 1=bwd
    const int b = blockIdx.x * ROWS_PB + rowi;

    const float* __restrict__ P = y_pred + (size_t)b * (size_t)(T_DIM * C_DIM);
    const int* __restrict__ lab = y_true + (size_t)b * L_DIM;

    // Labels for this lane's two odd states (s=4L+1 -> lab[2L], s=4L+3 -> lab[2L+1]).
    int l1 = lab[2 * lane], l3 = lab[2 * lane + 1];
    int col1 = max(0, min(C_DIM - 1, l1));
    int col3 = max(0, min(C_DIM - 1, l3));
    // skip(s) for odd s>=3: lab[j] != lab[j-1], j=(s-1)/2.
    float skF1 = (lane >= 1 && l1 != lab[2 * lane - 1]) ? 1.f : 0.f; // skip(4L+1)
    float skF3 = (l3 != l1) ? 1.f : 0.f;                             // skip(4L+3)
    float skB3 = (lane < 31 && lab[2 * lane + 2] != l3) ? 1.f : 0.f; // skip(4L+5)
    const float sk1 = dir ? skF3 : skF1;     // bwd slot1 uses skip(4L+3)
    const float sk3 = dir ? skB3 : skF3;
    const float t31f = (lane == 31) ? 1.f : 0.f;

    // state slots (alpha fwd / beta bwd); true value = a[k] * 2^E.
    // atop = state 128, warp-uniform, in lane 31's scale.
    float a[4];
#pragma unroll
    for (int k = 0; k < 4; ++k) a[k] = 0.f;
    float atop = 0.f;
    if (dir == 0) {
        if (lane == 0) { a[0] = P[BLANK] + EPSF; a[1] = P[col1] + EPSF; }
    } else {
        if (lane == 31) a[3] = 1.f;    // state 127
        atop = 1.f;                    // state 128
    }
    int E = 0;
    const bool bnd = (dir == 0) ? (lane == 0) : (lane == 31);
    float f = bnd ? 0.f : 1.f;

    float* wring = ring + warp * STG * CHF;

    // producer: coalesced cp.async of one 16-row chunk (6144 B)
    auto issue = [&](int i) {                 // i = 0..15 (warp-local order)
        int c = dir ? (NCHG - 1 - i) : i;     // global chunk id
        const float4* g = (const float4*)(P + (size_t)c * CHF);
        unsigned sa = (unsigned)__cvta_generic_to_shared(
            wring + (i & (STG - 1)) * CHF);
#pragma unroll
        for (int j = 0; j < 12; ++j) {        // 384 float4 / 32 lanes
            int idx = lane + 32 * j;
            asm volatile("cp.async.cg.shared.global [%0], [%1], 16;\n"
                         :: "r"(sa + idx * 16), "l"(g + idx));
        }
        asm volatile("cp.async.commit_group;\n" ::: "memory");
    };

    auto step_fwd = [&](float qb, float q1, float q3) {
        float a127 = __shfl_sync(FULLMASK, a[3], 31);       // old alpha(127)
        float am1  = __shfl_up_sync(FULLMASK, a[3], 1) * f; // alpha(4L-1)
        float n0 = (a[0] + am1) * qb;
        float n1 = fmaf(sk1, am1, a[1] + a[0]) * q1;
        float n2 = (a[2] + a[1]) * qb;
        float n3 = fmaf(sk3, a[1], a[3] + a[2]) * q3;
        atop = (atop + a127) * qb;                          // state 128
        a[0]=n0; a[1]=n1; a[2]=n2; a[3]=n3;
    };

    auto step_bwd = [&](float qb, float q1, float q3) {
        float g0 = qb*a[0], g1 = q1*a[1], g2 = qb*a[2], g3 = q3*a[3];
        float gt = qb * atop;                               // g(128)
        float gn0 = __shfl_down_sync(FULLMASK, g0, 1) * f;  // g(4L+4)
        float gn1 = __shfl_down_sync(FULLMASK, g1, 1) * f;  // g(4L+5)
        float n0 = g0 + g1;
        float n1 = fmaf(sk1, g3, g1 + g2);
        float n2 = g2 + g3;
        float n3 = fmaf(t31f, gt, fmaf(sk3, gn1, g3 + gn0));
        atop = gt;                                          // beta(128)
        a[0]=n0; a[1]=n1; a[2]=n2; a[3]=n3;
    };

    auto renorm = [&]() {
        float m = fmaxf(fmaxf(a[0], a[1]), fmaxf(a[2], a[3]));
        m = fmaxf(m, atop * t31f);          // lane 31 owns the top state
        bool ne = (m > 0.f);
        float fac = 1.f;
        if (ne) {
            int mb = __float_as_int(m) >> 23;
            if (mb == 0) {                           // denormal max: boost
                const float up = 0x1p126f;
#pragma unroll
                for (int k = 0; k < 4; ++k) a[k] *= up;
                fac *= up;
                E -= 126;
                m *= up;
                mb = __float_as_int(m) >> 23;
            }
            float scale = __int_as_float((254 - mb) << 23);   // exact 2^{-e}
#pragma unroll
            for (int k = 0; k < 4; ++k) a[k] *= scale;
            fac *= scale;
            E += mb - 127;
        }
        float fac31 = __shfl_sync(FULLMASK, fac, 31);
        atop *= fac31;                       // keep atop in lane31's scale
        unsigned bm = __ballot_sync(FULLMASK, ne);
        if (dir == 0) {          // mass flows low->high lanes
            unsigned below = bm & ((2u << lane) - 1u);
            int src = below ? (31 - __clz(below)) : lane;
            int Ead = __shfl_sync(FULLMASK, E, src);
            if (!ne) E = Ead;
            int Ep = __shfl_up_sync(FULLMASK, E, 1);
            int d = Ep - E;
            d = max(-127, min(120, d));
            f = (bnd || d <= -127) ? 0.f : __int_as_float((d + 127) << 23);
        } else {                 // mass flows high->low lanes
            unsigned up = bm & ~((1u << lane) - 1u);
            int src = up ? (__ffs(up) - 1) : lane;
            int Ead = __shfl_sync(FULLMASK, E, src);
            if (!ne) E = Ead;
            int Ep = __shfl_down_sync(FULLMASK, E, 1);
            int d = Ep - E;
            d = max(-127, min(120, d));
            f = (bnd || d <= -127) ? 0.f : __int_as_float((d + 127) << 23);
        }
    };

    // ---- pipeline: depth-3 prologue ----
    issue(0); issue(1); issue(2);
#pragma unroll 1
    for (int i = 0; i < NCH; ++i) {
        if (i + 3 < NCH) issue(i + 3);
        if (i < NCH - 3)
            asm volatile("cp.async.wait_group 3;\n" ::: "memory");
        else
            asm volatile("cp.async.wait_group 0;\n" ::: "memory");
        __syncwarp();

        // per-chunk gather bases (row offset folds into the LDS immediate)
        const float* sb = wring + (i & (STG - 1)) * CHF;
        const float* pB = sb + BLANK;
        const float* p1 = sb + col1;
        const float* p3 = sb + col3;

        if (dir == 0) {
            if (i == 0) {
#pragma unroll
                for (int j = 1; j < CH; ++j) {
                    step_fwd(pB[j*C_DIM]+EPSF, p1[j*C_DIM]+EPSF,
                             p3[j*C_DIM]+EPSF);
                    if (j == 7) renorm();      // 8-step cadence
                }
            } else {
#pragma unroll
                for (int j = 0; j < CH; ++j) {
                    step_fwd(pB[j*C_DIM]+EPSF, p1[j*C_DIM]+EPSF,
                             p3[j*C_DIM]+EPSF);
                    if (j == 7) renorm();
                }
            }
        } else {
#pragma unroll
            for (int j = 0; j < CH; ++j) {
                int r = CH - 1 - j;     // t = 511 - (i*16 + j)
                step_bwd(pB[r*C_DIM]+EPSF, p1[r*C_DIM]+EPSF,
                         p3[r*C_DIM]+EPSF);
                if (j == 7) renorm();
            }
        }
        renorm();                       // end-of-chunk (every 8 steps total)
    }

    // ---- combine: loss = -log( sum_{s=0..128} alpha_255(s)*beta_255(s) ) ----
    if (dir == 1) {
        float* rb = resB + (rowi * 32 + lane) * 5;
#pragma unroll
        for (int k = 0; k < 4; ++k) rb[k] = a[k];
        rb[4] = atop;                              // beta(128), lane31 scale
        resE[rowi * 32 + lane] = E;
    }
    __syncthreads();
    if (dir == 0) {
        const float* rb = resB + (rowi * 32 + lane) * 5;
        double sd = 0.0;
#pragma unroll
        for (int k = 0; k < 4; ++k)
            sd += (double)a[k] * (double)rb[k];
        sd += (double)(t31f * atop) * (double)rb[4];   // s=128 term, lane 31
        int X = E + resE[rowi * 32 + lane];
        bool valid = (sd > 0.0);
        int es = valid ? ilogb(sd) : 0;
        int key = valid ? (X + es) : -1000000000;
        int M = key;
#pragma unroll
        for (int o = 16; o > 0; o >>= 1)
            M = max(M, __shfl_xor_sync(FULLMASK, M, o));
        float term = 0.f;
        if (valid) {
            double mant = scalbn(sd, -es);     // in [1,2)
            int d = key - M;
            if (d >= -126) term = (float)mant * __int_as_float((d + 127) << 23);
        }
#pragma unroll
        for (int o = 16; o > 0; o >>= 1)
            term += __shfl_xor_sync(FULLMASK, term, o);
        if (lane == 0)
            out[b] = (float)(-(log((double)term)
                              + (double)M * 0.6931471805599453));
    }
}

extern "C" void kernel_launch(void* const* d_in, const int* in_sizes, int n_in,
                              void* d_out, int out_size)
{
    int iy = 0, ip = 1;
    if (n_in >= 2 && in_sizes[0] > in_sizes[1]) { iy = 1; ip = 0; }
    const int* y_true = (const int*)d_in[iy];
    const float* y_pred = (const float*)d_in[ip];
    float* out = (float*)d_out;
    int B = in_sizes[iy] / L_DIM;                 // 512
    static bool configured = false;
    if (!configured) {
        cudaFuncSetAttribute(ctc_fb_kernel,
                             cudaFuncAttributeMaxDynamicSharedMemorySize,
                             SMEM_BYTES);
        configured = true;
    }
    int grid = (B + ROWS_PB - 1) / ROWS_PB;       // 128
    ctc_fb_kernel<<<grid, 256, SMEM_BYTES>>>(y_true, y_pred, out, B);
}